// round 4
// baseline (speedup 1.0000x reference)
#include <cuda_runtime.h>
#include <cuda_fp16.h>
#include <cuda_bf16.h>
#include <cstdint>

// ---------------------------------------------------------------------------
// EstimateAdj:
//   h    = relu(features @ W1 + b1)   [N,128]->[N,64]
//   reps = h @ W2 + b2                [N,64]
//   pw[e] = relu(dot(reps[ei0[e]], reps[ei1[e]]))  e < Eo
// Output (float32 concat): reps | pw | total_edge_index | edge_index
//
// R4 changes vs R3 (110.8us):
//  - MLP inner loops use packed fma.rn.f32x2 (FFMA2): 2 fp32 MACs/instr,
//    bit-identical fp32 results. Compute floor 72us -> 36us.
// ---------------------------------------------------------------------------

#define MLP_THREADS 256
#define NPB 64            // nodes per MLP block
#define HS_STRIDE 68      // padded h-tile stride (floats)
#define N_MAX 100000

typedef unsigned long long u64;

__device__ __forceinline__ u64 pack2(float lo, float hi) {
    u64 r;
    asm("mov.b64 %0, {%1, %2};" : "=l"(r) : "f"(lo), "f"(hi));
    return r;
}
__device__ __forceinline__ u64 fma2(u64 a, u64 b, u64 c) {
    u64 d;
    asm("fma.rn.f32x2 %0, %1, %2, %3;" : "=l"(d) : "l"(a), "l"(b), "l"(c));
    return d;
}
__device__ __forceinline__ float2 unpack2(u64 v) {
    float2 r;
    asm("mov.b64 {%0, %1}, %2;" : "=f"(r.x), "=f"(r.y) : "l"(v));
    return r;
}

// fp16 shadow of reps (32 half2 per node = 128B/row) for the edge gather
__device__ __half2 g_reps_h[N_MAX * 32];

// Fused 2-layer MLP + (role-split) index copy.
__global__ void __launch_bounds__(MLP_THREADS)
mlp_plus_copy_kernel(const float* __restrict__ feat,
                     const float* __restrict__ W1, const float* __restrict__ b1,
                     const float* __restrict__ W2, const float* __restrict__ b2,
                     float* __restrict__ reps, int N, int mlp_blocks,
                     const int* __restrict__ ei, const int* __restrict__ pei,
                     long long Eo, long long Ec,
                     float* __restrict__ out_tei, float* __restrict__ out_ei)
{
    const int tx = threadIdx.x;

    if (blockIdx.x >= mlp_blocks) {
        // ---------------- index copy role (vectorized x4) ----------------
        long long i = ((long long)(blockIdx.x - mlp_blocks) * MLP_THREADS + tx) * 4;
        long long Et = Eo + Ec;
        if (i < Eo) {
            int4 v0 = *(const int4*)(ei + i);
            int4 v1 = *(const int4*)(ei + Eo + i);
            float4 f0 = make_float4((float)v0.x, (float)v0.y, (float)v0.z, (float)v0.w);
            float4 f1 = make_float4((float)v1.x, (float)v1.y, (float)v1.z, (float)v1.w);
            *(float4*)(out_tei + i)      = f0;
            *(float4*)(out_tei + Et + i) = f1;
            *(float4*)(out_ei + i)       = f0;
            *(float4*)(out_ei + Eo + i)  = f1;
        }
        if (i < Ec) {
            int4 v0 = *(const int4*)(pei + i);
            int4 v1 = *(const int4*)(pei + Ec + i);
            float4 f0 = make_float4((float)v0.x, (float)v0.y, (float)v0.z, (float)v0.w);
            float4 f1 = make_float4((float)v1.x, (float)v1.y, (float)v1.z, (float)v1.w);
            *(float4*)(out_tei + Eo + i)      = f0;
            *(float4*)(out_tei + Et + Eo + i) = f1;
        }
        return;
    }

    // ---------------- MLP role ----------------
    extern __shared__ float sh[];
    float* W1s = sh;                 // 128*64 floats (32 KB)
    float* W2s = sh + 8192;          // 64*64 floats (16 KB)
    float* hs  = sh;                 // h tile reuses W1s region after GEMM1

    {
        const float4* w1g = (const float4*)W1;
        float4* w1sv = (float4*)W1s;
        #pragma unroll
        for (int i = 0; i < 8; i++) w1sv[tx + 256 * i] = w1g[tx + 256 * i];
        const float4* w2g = (const float4*)W2;
        float4* w2sv = (float4*)W2s;
        #pragma unroll
        for (int i = 0; i < 4; i++) w2sv[tx + 256 * i] = w2g[tx + 256 * i];
    }
    __syncthreads();

    const int c = tx & 15;   // cols [c*4, c*4+4)
    const int r = tx >> 4;   // nodes [r*4, r*4+4) within block
    const int nbase = blockIdx.x * NPB + r * 4;

    // packed accumulators: acc2[i][0] = cols {c*4, c*4+1}, acc2[i][1] = {c*4+2, c*4+3}
    u64 acc2[4][2];
    #pragma unroll
    for (int i = 0; i < 4; i++) { acc2[i][0] = 0ull; acc2[i][1] = 0ull; }

    // ---- GEMM1: h = X @ W1, K=128 (packed f32x2) ----
    #pragma unroll 4
    for (int k4 = 0; k4 < 32; k4++) {
        float4 f[4];
        #pragma unroll
        for (int i = 0; i < 4; i++) {
            int n = nbase + i;
            f[i] = (n < N) ? *(const float4*)(feat + (size_t)n * 128 + k4 * 4)
                           : make_float4(0.f, 0.f, 0.f, 0.f);
        }
        #pragma unroll
        for (int kk = 0; kk < 4; kk++) {
            float4 w = *(const float4*)(W1s + (k4 * 4 + kk) * 64 + c * 4);
            u64 w01 = pack2(w.x, w.y);
            u64 w23 = pack2(w.z, w.w);
            #pragma unroll
            for (int i = 0; i < 4; i++) {
                float fv = (kk == 0) ? f[i].x : (kk == 1) ? f[i].y
                         : (kk == 2) ? f[i].z : f[i].w;
                u64 fd = pack2(fv, fv);
                acc2[i][0] = fma2(fd, w01, acc2[i][0]);
                acc2[i][1] = fma2(fd, w23, acc2[i][1]);
            }
        }
    }

    __syncthreads();  // all reads of W1s done before h overwrites it

    {
        float4 bb = *(const float4*)(b1 + c * 4);
        #pragma unroll
        for (int i = 0; i < 4; i++) {
            float2 lo = unpack2(acc2[i][0]);
            float2 hi = unpack2(acc2[i][1]);
            float4 hv;
            hv.x = fmaxf(lo.x + bb.x, 0.f);
            hv.y = fmaxf(lo.y + bb.y, 0.f);
            hv.z = fmaxf(hi.x + bb.z, 0.f);
            hv.w = fmaxf(hi.y + bb.w, 0.f);
            *(float4*)(hs + (r * 4 + i) * HS_STRIDE + c * 4) = hv;
        }
    }
    __syncthreads();

    // ---- GEMM2: reps = h @ W2, K=64 (packed f32x2) ----
    #pragma unroll
    for (int i = 0; i < 4; i++) { acc2[i][0] = 0ull; acc2[i][1] = 0ull; }

    #pragma unroll 4
    for (int k4 = 0; k4 < 16; k4++) {
        float4 h4[4];
        #pragma unroll
        for (int i = 0; i < 4; i++)
            h4[i] = *(const float4*)(hs + (r * 4 + i) * HS_STRIDE + k4 * 4);
        #pragma unroll
        for (int kk = 0; kk < 4; kk++) {
            float4 w = *(const float4*)(W2s + (k4 * 4 + kk) * 64 + c * 4);
            u64 w01 = pack2(w.x, w.y);
            u64 w23 = pack2(w.z, w.w);
            #pragma unroll
            for (int i = 0; i < 4; i++) {
                float hv = (kk == 0) ? h4[i].x : (kk == 1) ? h4[i].y
                         : (kk == 2) ? h4[i].z : h4[i].w;
                u64 hd = pack2(hv, hv);
                acc2[i][0] = fma2(hd, w01, acc2[i][0]);
                acc2[i][1] = fma2(hd, w23, acc2[i][1]);
            }
        }
    }

    {
        float4 bb = *(const float4*)(b2 + c * 4);
        #pragma unroll
        for (int i = 0; i < 4; i++) {
            int n = nbase + i;
            if (n < N) {
                float2 lo = unpack2(acc2[i][0]);
                float2 hi = unpack2(acc2[i][1]);
                float4 o;
                o.x = lo.x + bb.x;
                o.y = lo.y + bb.y;
                o.z = hi.x + bb.z;
                o.w = hi.y + bb.w;
                *(float4*)(reps + (size_t)n * 64 + c * 4) = o;
                // fp16 shadow for the edge gather
                __half2 h0 = __floats2half2_rn(o.x, o.y);
                __half2 h1 = __floats2half2_rn(o.z, o.w);
                g_reps_h[(size_t)n * 32 + c * 2]     = h0;
                g_reps_h[(size_t)n * 32 + c * 2 + 1] = h1;
            }
        }
    }
}

__device__ __forceinline__ float dot8h(uint4 a, uint4 b) {
    const __half2* pa = (const __half2*)&a;
    const __half2* pb = (const __half2*)&b;
    float acc = 0.f;
    #pragma unroll
    for (int j = 0; j < 4; j++) {
        float2 x = __half22float2(pa[j]);
        float2 y = __half22float2(pb[j]);
        acc = fmaf(x.x, y.x, acc);
        acc = fmaf(x.y, y.y, acc);
    }
    return acc;
}

// Edge dot products on the fp16 shadow: 4 threads/edge, fp32 accumulate.
__global__ void __launch_bounds__(256)
edge_dot_kernel(const int* __restrict__ ei, long long Eo,
                float* __restrict__ pw, int N)
{
    long long t = (long long)blockIdx.x * blockDim.x + threadIdx.x;
    long long e = t >> 2;
    int l = (int)(t & 3);
    if (e >= Eo) return;

    int i0 = ei[e];
    int i1 = ei[e + Eo];
    i0 = min(max(i0, 0), N - 1);   // defensive clamp, branch-free
    i1 = min(max(i1, 0), N - 1);

    const uint4* A = (const uint4*)(g_reps_h + (size_t)i0 * 32);
    const uint4* B = (const uint4*)(g_reps_h + (size_t)i1 * 32);

    uint4 a0 = A[l * 2], a1 = A[l * 2 + 1];
    uint4 b0 = B[l * 2], b1 = B[l * 2 + 1];

    float acc = dot8h(a0, b0) + dot8h(a1, b1);

    acc += __shfl_xor_sync(0xffffffffu, acc, 2);
    acc += __shfl_xor_sync(0xffffffffu, acc, 1);

    if (l == 0) pw[e] = fmaxf(acc, 0.f);
}

extern "C" void kernel_launch(void* const* d_in, const int* in_sizes, int n_in,
                              void* d_out, int out_size)
{
    const float* feat = (const float*)d_in[0];
    const int*   ei   = (const int*)d_in[1];
    const int*   pei  = (const int*)d_in[2];
    const float* W1   = (const float*)d_in[3];
    const float* b1   = (const float*)d_in[4];
    const float* W2   = (const float*)d_in[5];
    const float* b2   = (const float*)d_in[6];
    float* out = (float*)d_out;

    const int N        = in_sizes[0] / 128;
    const long long Eo = in_sizes[1] / 2;
    const long long Ec = in_sizes[2] / 2;

    float* reps    = out;
    float* pw      = out + (size_t)N * 64;
    float* out_tei = pw + Eo;
    float* out_ei  = out_tei + 2 * (Eo + Ec);

    const int shmem = (8192 + 4096) * (int)sizeof(float);  // 48 KB, default limit
    int mlp_blocks = (N + NPB - 1) / NPB;
    long long copy_items = (Eo > Ec ? Eo : Ec);
    int copy_blocks = (int)((copy_items + MLP_THREADS * 4 - 1) / (MLP_THREADS * 4));

    mlp_plus_copy_kernel<<<mlp_blocks + copy_blocks, MLP_THREADS, shmem>>>(
        feat, W1, b1, W2, b2, reps, N, mlp_blocks,
        ei, pei, Eo, Ec, out_tei, out_ei);

    long long edge_threads = Eo * 4;
    int edge_blocks = (int)((edge_threads + 255) / 256);
    edge_dot_kernel<<<edge_blocks, 256>>>(ei, Eo, pw, N);
}

// round 6
// speedup vs baseline: 1.3752x; 1.3752x over previous
#include <cuda_runtime.h>
#include <cuda_fp16.h>
#include <cuda_bf16.h>
#include <cstdint>

// ---------------------------------------------------------------------------
// EstimateAdj:
//   h    = relu(features @ W1 + b1)   [N,128]->[N,64]
//   reps = h @ W2 + b2                [N,64]
//   pw[e] = relu(dot(reps[ei0[e]], reps[ei1[e]]))  e < Eo
// Output (float32 concat): reps | pw | total_edge_index | edge_index
//
// R6 vs R5 (failed): fix B-fragment addressing — per-lane column is
// (n_tile*8 + groupID), not n_tile. Everything else identical to R5.
// ---------------------------------------------------------------------------

#define MLP_THREADS 256
#define NODES_PER_BLK 128
#define N_MAX 100000

typedef unsigned int u32;

// fp16 shadow of reps (32 half2 per node = 128B/row) for the edge gather
__device__ __half2 g_reps_h[N_MAX * 32];

// smem layout (bytes):
//  Wt1h [64][136] bf16 : 0      .. 17408
//  Wt1l [64][136] bf16 : 17408  .. 34816
//  Wt2h [64][72]  bf16 : 34816  .. 44032
//  Wt2l [64][72]  bf16 : 44032  .. 53248
//  b1s  [64] f32       : 53248  .. 53504
//  b2s  [64] f32       : 53504  .. 53760
#define SMEM_BYTES 53760
#define W1_STRIDE 136   // 68 words; (68*(8n+g)+t)%32 = (4g+t)%32 -> conflict-free
#define W2_STRIDE 72    // 36 words; same property

__device__ __forceinline__ void mma_bf16(float* c, const u32* a, u32 b0, u32 b1) {
    asm volatile(
        "mma.sync.aligned.m16n8k16.row.col.f32.bf16.bf16.f32 "
        "{%0,%1,%2,%3}, {%4,%5,%6,%7}, {%8,%9}, {%0,%1,%2,%3};"
        : "+f"(c[0]), "+f"(c[1]), "+f"(c[2]), "+f"(c[3])
        : "r"(a[0]), "r"(a[1]), "r"(a[2]), "r"(a[3]), "r"(b0), "r"(b1));
}

// split (x,y) into bf16 hi pair + bf16 residual pair (packed, x in low half)
__device__ __forceinline__ void split2(float x, float y, u32& hi, u32& lo) {
    __nv_bfloat16 bx = __float2bfloat16(x), by = __float2bfloat16(y);
    hi = ((u32)__bfloat16_as_ushort(by) << 16) | (u32)__bfloat16_as_ushort(bx);
    float rx = x - __bfloat162float(bx);
    float ry = y - __bfloat162float(by);
    __nv_bfloat16 cx = __float2bfloat16(rx), cy = __float2bfloat16(ry);
    lo = ((u32)__bfloat16_as_ushort(cy) << 16) | (u32)__bfloat16_as_ushort(cx);
}

// Fused MMA MLP + (role-split) index copy.
__global__ void __launch_bounds__(MLP_THREADS)
mlp_mma_kernel(const float* __restrict__ feat,
               const float* __restrict__ W1, const float* __restrict__ b1,
               const float* __restrict__ W2, const float* __restrict__ b2,
               float* __restrict__ reps, int N, int mlp_blocks,
               const int* __restrict__ ei, const int* __restrict__ pei,
               long long Eo, long long Ec,
               float* __restrict__ out_tei, float* __restrict__ out_ei)
{
    const int tx = threadIdx.x;

    if (blockIdx.x >= mlp_blocks) {
        // ---------------- index copy role (vectorized x4) ----------------
        long long i = ((long long)(blockIdx.x - mlp_blocks) * MLP_THREADS + tx) * 4;
        long long Et = Eo + Ec;
        if (i < Eo) {
            int4 v0 = *(const int4*)(ei + i);
            int4 v1 = *(const int4*)(ei + Eo + i);
            float4 f0 = make_float4((float)v0.x, (float)v0.y, (float)v0.z, (float)v0.w);
            float4 f1 = make_float4((float)v1.x, (float)v1.y, (float)v1.z, (float)v1.w);
            *(float4*)(out_tei + i)      = f0;
            *(float4*)(out_tei + Et + i) = f1;
            *(float4*)(out_ei + i)       = f0;
            *(float4*)(out_ei + Eo + i)  = f1;
        }
        if (i < Ec) {
            int4 v0 = *(const int4*)(pei + i);
            int4 v1 = *(const int4*)(pei + Ec + i);
            float4 f0 = make_float4((float)v0.x, (float)v0.y, (float)v0.z, (float)v0.w);
            float4 f1 = make_float4((float)v1.x, (float)v1.y, (float)v1.z, (float)v1.w);
            *(float4*)(out_tei + Eo + i)      = f0;
            *(float4*)(out_tei + Et + Eo + i) = f1;
        }
        return;
    }

    // ---------------- MLP role ----------------
    extern __shared__ char smc[];
    __nv_bfloat16* Wt1h = (__nv_bfloat16*)(smc);
    __nv_bfloat16* Wt1l = (__nv_bfloat16*)(smc + 17408);
    __nv_bfloat16* Wt2h = (__nv_bfloat16*)(smc + 34816);
    __nv_bfloat16* Wt2l = (__nv_bfloat16*)(smc + 44032);
    float* b1s = (float*)(smc + 53248);
    float* b2s = (float*)(smc + 53504);

    // Prologue: split W1, W2 to transposed bf16 hi/lo planes.
    for (int idx = tx; idx < 128 * 64; idx += MLP_THREADS) {
        int k = idx >> 6, n = idx & 63;
        float w = W1[idx];
        __nv_bfloat16 hi = __float2bfloat16(w);
        Wt1h[n * W1_STRIDE + k] = hi;
        Wt1l[n * W1_STRIDE + k] = __float2bfloat16(w - __bfloat162float(hi));
    }
    for (int idx = tx; idx < 64 * 64; idx += MLP_THREADS) {
        int k = idx >> 6, n = idx & 63;
        float w = W2[idx];
        __nv_bfloat16 hi = __float2bfloat16(w);
        Wt2h[n * W2_STRIDE + k] = hi;
        Wt2l[n * W2_STRIDE + k] = __float2bfloat16(w - __bfloat162float(hi));
    }
    if (tx < 64) { b1s[tx] = b1[tx]; b2s[tx] = b2[tx]; }
    __syncthreads();

    const int warp = tx >> 5, lane = tx & 31;
    const int g = lane >> 2, t = lane & 3;
    const int r0 = blockIdx.x * NODES_PER_BLK + warp * 16 + g;
    const int r1 = r0 + 8;
    const bool v0 = r0 < N, v1 = r1 < N;
    const float* f0p = feat + (size_t)(v0 ? r0 : 0) * 128 + t * 2;
    const float* f1p = feat + (size_t)(v1 ? r1 : 0) * 128 + t * 2;

    // ---- GEMM1: C[8 n-tiles][4] over K=128 (8 k-steps), 3-pass bf16 ----
    float C[8][4];
    #pragma unroll
    for (int n = 0; n < 8; n++)
        #pragma unroll
        for (int i = 0; i < 4; i++) C[n][i] = 0.f;

    #pragma unroll 2
    for (int kt = 0; kt < 8; kt++) {
        float2 x00 = v0 ? *(const float2*)(f0p + kt * 16)     : make_float2(0.f, 0.f);
        float2 x01 = v0 ? *(const float2*)(f0p + kt * 16 + 8) : make_float2(0.f, 0.f);
        float2 x10 = v1 ? *(const float2*)(f1p + kt * 16)     : make_float2(0.f, 0.f);
        float2 x11 = v1 ? *(const float2*)(f1p + kt * 16 + 8) : make_float2(0.f, 0.f);
        u32 ah[4], al[4];
        split2(x00.x, x00.y, ah[0], al[0]);
        split2(x10.x, x10.y, ah[1], al[1]);
        split2(x01.x, x01.y, ah[2], al[2]);
        split2(x11.x, x11.y, ah[3], al[3]);

        const int kb = kt * 16 + t * 2;
        #pragma unroll
        for (int n = 0; n < 8; n++) {
            const __nv_bfloat16* wh = Wt1h + (n * 8 + g) * W1_STRIDE + kb;
            const __nv_bfloat16* wl = Wt1l + (n * 8 + g) * W1_STRIDE + kb;
            u32 bh0 = *(const u32*)(wh);
            u32 bh1 = *(const u32*)(wh + 8);
            u32 bl0 = *(const u32*)(wl);
            u32 bl1 = *(const u32*)(wl + 8);
            mma_bf16(C[n], ah, bh0, bh1);
            mma_bf16(C[n], ah, bl0, bl1);
            mma_bf16(C[n], al, bh0, bh1);
        }
    }

    // bias + relu -> h (kept in registers), then split into GEMM2 A-frags.
    // C-frag lane layout == A-frag lane layout: a-frags for k-step kt2 come
    // from n-tiles 2*kt2 (k%16 in [0,8)) and 2*kt2+1 (k%16 in [8,16)).
    #pragma unroll
    for (int n = 0; n < 8; n++) {
        float bb0 = b1s[n * 8 + t * 2];
        float bb1 = b1s[n * 8 + t * 2 + 1];
        C[n][0] = fmaxf(C[n][0] + bb0, 0.f);
        C[n][1] = fmaxf(C[n][1] + bb1, 0.f);
        C[n][2] = fmaxf(C[n][2] + bb0, 0.f);
        C[n][3] = fmaxf(C[n][3] + bb1, 0.f);
    }

    u32 a2h[4][4], a2l[4][4];
    #pragma unroll
    for (int kt = 0; kt < 4; kt++) {
        split2(C[2 * kt][0],     C[2 * kt][1],     a2h[kt][0], a2l[kt][0]);
        split2(C[2 * kt][2],     C[2 * kt][3],     a2h[kt][1], a2l[kt][1]);
        split2(C[2 * kt + 1][0], C[2 * kt + 1][1], a2h[kt][2], a2l[kt][2]);
        split2(C[2 * kt + 1][2], C[2 * kt + 1][3], a2h[kt][3], a2l[kt][3]);
    }

    // ---- GEMM2: D[8][4] over K=64 (4 k-steps), 3-pass bf16 ----
    float D[8][4];
    #pragma unroll
    for (int n = 0; n < 8; n++)
        #pragma unroll
        for (int i = 0; i < 4; i++) D[n][i] = 0.f;

    #pragma unroll
    for (int kt = 0; kt < 4; kt++) {
        const int kb = kt * 16 + t * 2;
        #pragma unroll
        for (int n = 0; n < 8; n++) {
            const __nv_bfloat16* wh = Wt2h + (n * 8 + g) * W2_STRIDE + kb;
            const __nv_bfloat16* wl = Wt2l + (n * 8 + g) * W2_STRIDE + kb;
            u32 bh0 = *(const u32*)(wh);
            u32 bh1 = *(const u32*)(wh + 8);
            u32 bl0 = *(const u32*)(wl);
            u32 bl1 = *(const u32*)(wl + 8);
            mma_bf16(D[n], a2h[kt], bh0, bh1);
            mma_bf16(D[n], a2h[kt], bl0, bl1);
            mma_bf16(D[n], a2l[kt], bh0, bh1);
        }
    }

    // Epilogue: bias, store reps (fp32) + fp16 shadow.
    #pragma unroll
    for (int n = 0; n < 8; n++) {
        int c0 = n * 8 + t * 2;
        float bb0 = b2s[c0], bb1 = b2s[c0 + 1];
        if (v0) {
            float2 o = make_float2(D[n][0] + bb0, D[n][1] + bb1);
            *(float2*)(reps + (size_t)r0 * 64 + c0) = o;
            g_reps_h[(size_t)r0 * 32 + (c0 >> 1)] = __floats2half2_rn(o.x, o.y);
        }
        if (v1) {
            float2 o = make_float2(D[n][2] + bb0, D[n][3] + bb1);
            *(float2*)(reps + (size_t)r1 * 64 + c0) = o;
            g_reps_h[(size_t)r1 * 32 + (c0 >> 1)] = __floats2half2_rn(o.x, o.y);
        }
    }
}

__device__ __forceinline__ float dot8h(uint4 a, uint4 b) {
    const __half2* pa = (const __half2*)&a;
    const __half2* pb = (const __half2*)&b;
    float acc = 0.f;
    #pragma unroll
    for (int j = 0; j < 4; j++) {
        float2 x = __half22float2(pa[j]);
        float2 y = __half22float2(pb[j]);
        acc = fmaf(x.x, y.x, acc);
        acc = fmaf(x.y, y.y, acc);
    }
    return acc;
}

// Edge dot products on the fp16 shadow: 4 threads/edge, fp32 accumulate.
__global__ void __launch_bounds__(256)
edge_dot_kernel(const int* __restrict__ ei, long long Eo,
                float* __restrict__ pw, int N)
{
    long long t = (long long)blockIdx.x * blockDim.x + threadIdx.x;
    long long e = t >> 2;
    int l = (int)(t & 3);
    if (e >= Eo) return;

    int i0 = ei[e];
    int i1 = ei[e + Eo];
    i0 = min(max(i0, 0), N - 1);
    i1 = min(max(i1, 0), N - 1);

    const uint4* A = (const uint4*)(g_reps_h + (size_t)i0 * 32);
    const uint4* B = (const uint4*)(g_reps_h + (size_t)i1 * 32);

    uint4 a0 = A[l * 2], a1 = A[l * 2 + 1];
    uint4 b0 = B[l * 2], b1 = B[l * 2 + 1];

    float acc = dot8h(a0, b0) + dot8h(a1, b1);

    acc += __shfl_xor_sync(0xffffffffu, acc, 2);
    acc += __shfl_xor_sync(0xffffffffu, acc, 1);

    if (l == 0) pw[e] = fmaxf(acc, 0.f);
}

extern "C" void kernel_launch(void* const* d_in, const int* in_sizes, int n_in,
                              void* d_out, int out_size)
{
    const float* feat = (const float*)d_in[0];
    const int*   ei   = (const int*)d_in[1];
    const int*   pei  = (const int*)d_in[2];
    const float* W1   = (const float*)d_in[3];
    const float* b1   = (const float*)d_in[4];
    const float* W2   = (const float*)d_in[5];
    const float* b2   = (const float*)d_in[6];
    float* out = (float*)d_out;

    const int N        = in_sizes[0] / 128;
    const long long Eo = in_sizes[1] / 2;
    const long long Ec = in_sizes[2] / 2;

    float* reps    = out;
    float* pw      = out + (size_t)N * 64;
    float* out_tei = pw + Eo;
    float* out_ei  = out_tei + 2 * (Eo + Ec);

    cudaFuncSetAttribute(mlp_mma_kernel,
                         cudaFuncAttributeMaxDynamicSharedMemorySize, SMEM_BYTES);

    int mlp_blocks = (N + NODES_PER_BLK - 1) / NODES_PER_BLK;
    long long copy_items = (Eo > Ec ? Eo : Ec);
    int copy_blocks = (int)((copy_items + MLP_THREADS * 4 - 1) / (MLP_THREADS * 4));

    mlp_mma_kernel<<<mlp_blocks + copy_blocks, MLP_THREADS, SMEM_BYTES>>>(
        feat, W1, b1, W2, b2, reps, N, mlp_blocks,
        ei, pei, Eo, Ec, out_tei, out_ei);

    long long edge_threads = Eo * 4;
    int edge_blocks = (int)((edge_threads + 255) / 256);
    edge_dot_kernel<<<edge_blocks, 256>>>(ei, Eo, pw, N);
}